// round 1
// baseline (speedup 1.0000x reference)
#include <cuda_runtime.h>
#include <math.h>

#define BATCH 64
#define SEQ 512
#define INPUT_DIM 512
#define HIDDEN 128
#define G3 384            // 3*HIDDEN
#define NUM_LAYERS 5
#define OUTPUT_DIM 96

typedef unsigned long long ull;

// ---------------- scratch (no allocs allowed) ----------------
__device__ float g_gx[BATCH * SEQ * G3];        // per-layer input gates
__device__ float g_ya[BATCH * SEQ * HIDDEN];    // ping
__device__ float g_yb[BATCH * SEQ * HIDDEN];    // pong

// ---------------- packed f32x2 helpers ----------------
__device__ __forceinline__ ull pk2(float a, float b) {
    ull r; asm("mov.b64 %0, {%1, %2};" : "=l"(r) : "f"(a), "f"(b)); return r;
}
__device__ __forceinline__ void upk2(ull v, float& a, float& b) {
    asm("mov.b64 {%0, %1}, %2;" : "=f"(a), "=f"(b) : "l"(v));
}
__device__ __forceinline__ ull ffma2(ull a, ull b, ull c) {
    ull d; asm("fma.rn.f32x2 %0, %1, %2, %3;" : "=l"(d) : "l"(a), "l"(b), "l"(c)); return d;
}

__device__ __forceinline__ float sigm(float x) {
    return 1.0f / (1.0f + __expf(-x));
}

// ---------------- GEMM: C[M x 384] = A[M x K] * W[384 x K]^T + bias ----------------
// BM=64, BN=64, BK=16, 256 threads, thread tile 4x4, packed f32x2 FMAs.
__global__ __launch_bounds__(256) void gemm_nt_kernel(
    const float* __restrict__ A, const float* __restrict__ W,
    const float* __restrict__ bias, float* __restrict__ C,
    int M, int K)
{
    __shared__ __align__(16) float Ast[16][64];
    __shared__ __align__(16) float Bst[16][64];

    const int tid = threadIdx.x;
    const int m0 = blockIdx.y * 64;
    const int n0 = blockIdx.x * 64;

    const int lrow = tid >> 2;          // 0..63
    const int lkc  = (tid & 3) << 2;    // 0,4,8,12

    const float* Ap = A + (size_t)(m0 + lrow) * K + lkc;
    const float* Wp = W + (size_t)(n0 + lrow) * K + lkc;

    const int tx = tid & 15;            // 0..15 (cols)
    const int ty = tid >> 4;            // 0..15 (rows)

    ull acc[4][2];
#pragma unroll
    for (int i = 0; i < 4; i++) { acc[i][0] = pk2(0.f, 0.f); acc[i][1] = pk2(0.f, 0.f); }

    float4 av = *(const float4*)(Ap);
    float4 bv = *(const float4*)(Wp);

    for (int kt = 0; kt < K; kt += 16) {
        __syncthreads();
        Ast[lkc + 0][lrow] = av.x; Ast[lkc + 1][lrow] = av.y;
        Ast[lkc + 2][lrow] = av.z; Ast[lkc + 3][lrow] = av.w;
        Bst[lkc + 0][lrow] = bv.x; Bst[lkc + 1][lrow] = bv.y;
        Bst[lkc + 2][lrow] = bv.z; Bst[lkc + 3][lrow] = bv.w;
        __syncthreads();

        if (kt + 16 < K) {
            av = *(const float4*)(Ap + kt + 16);
            bv = *(const float4*)(Wp + kt + 16);
        }

#pragma unroll
        for (int k = 0; k < 16; k++) {
            float4 a4 = *(const float4*)&Ast[k][ty << 2];
            ulonglong2 b2 = *(const ulonglong2*)&Bst[k][tx << 2];
            ull pa;
            pa = pk2(a4.x, a4.x);
            acc[0][0] = ffma2(pa, b2.x, acc[0][0]); acc[0][1] = ffma2(pa, b2.y, acc[0][1]);
            pa = pk2(a4.y, a4.y);
            acc[1][0] = ffma2(pa, b2.x, acc[1][0]); acc[1][1] = ffma2(pa, b2.y, acc[1][1]);
            pa = pk2(a4.z, a4.z);
            acc[2][0] = ffma2(pa, b2.x, acc[2][0]); acc[2][1] = ffma2(pa, b2.y, acc[2][1]);
            pa = pk2(a4.w, a4.w);
            acc[3][0] = ffma2(pa, b2.x, acc[3][0]); acc[3][1] = ffma2(pa, b2.y, acc[3][1]);
        }
    }

    // epilogue: add bias, store
#pragma unroll
    for (int i = 0; i < 4; i++) {
        int m = m0 + (ty << 2) + i;
        float c0, c1, c2, c3;
        upk2(acc[i][0], c0, c1);
        upk2(acc[i][1], c2, c3);
        int n = n0 + (tx << 2);
        float* Cp = C + (size_t)m * G3 + n;
        Cp[0] = c0 + bias[n + 0];
        Cp[1] = c1 + bias[n + 1];
        Cp[2] = c2 + bias[n + 2];
        Cp[3] = c3 + bias[n + 3];
    }
}

// ---------------- GRU recurrence: one CTA per batch element ----------------
// 384 threads; thread j owns gate-row j of w_hh (128 weights in registers,
// packed as 64 f32x2). Per step: gh[j] = b_hh[j] + w_hh[j,:]·h, then 128
// threads combine gates. 2 barriers/step.
__global__ __launch_bounds__(384, 1) void gru_rec_kernel(
    const float* __restrict__ w_hh,   // [384][128] for this layer
    const float* __restrict__ b_hh,   // [384]
    float* __restrict__ y)            // [BATCH][SEQ][HIDDEN]
{
    __shared__ __align__(16) float h_s[2][HIDDEN];
    __shared__ float gh_s[G3];

    const int b = blockIdx.x;
    const int j = threadIdx.x;

    // load this thread's weight row into registers (packed pairs)
    ull w2[64];
    {
        const float4* wr = (const float4*)(w_hh + (size_t)j * HIDDEN);
#pragma unroll
        for (int k4 = 0; k4 < 32; k4++) {
            float4 v = wr[k4];
            w2[2 * k4 + 0] = pk2(v.x, v.y);
            w2[2 * k4 + 1] = pk2(v.z, v.w);
        }
    }
    const float bh = b_hh[j];

    if (j < HIDDEN) { h_s[0][j] = 0.0f; }
    __syncthreads();

    const float* gxb = g_gx + (size_t)b * SEQ * G3;
    float* yb = y + (size_t)b * SEQ * HIDDEN;

    int cur = 0;
    for (int t = 0; t < SEQ; t++) {
        const float* gxt = gxb + t * G3;
        float xr = 0.f, xz = 0.f, xn = 0.f;
        if (j < HIDDEN) {
            xr = gxt[j];
            xz = gxt[j + HIDDEN];
            xn = gxt[j + 2 * HIDDEN];
        }

        // gh[j] = bh + w_row_j · h
        ull a0 = pk2(0.f, 0.f), a1 = pk2(0.f, 0.f);
        const ulonglong2* h2 = (const ulonglong2*)h_s[cur];
#pragma unroll
        for (int k4 = 0; k4 < 32; k4++) {
            ulonglong2 hv = h2[k4];
            a0 = ffma2(w2[2 * k4 + 0], hv.x, a0);
            a1 = ffma2(w2[2 * k4 + 1], hv.y, a1);
        }
        float l0, u0, l1, u1;
        upk2(a0, l0, u0);
        upk2(a1, l1, u1);
        gh_s[j] = bh + ((l0 + u0) + (l1 + u1));
        __syncthreads();

        if (j < HIDDEN) {
            float r = sigm(xr + gh_s[j]);
            float z = sigm(xz + gh_s[j + HIDDEN]);
            float n = tanhf(xn + r * gh_s[j + 2 * HIDDEN]);
            float hn = (1.0f - z) * n + z * h_s[cur][j];
            h_s[cur ^ 1][j] = hn;
            yb[t * HIDDEN + j] = hn;
        }
        __syncthreads();
        cur ^= 1;
    }
}

// ---------------- final FC on last timestep ----------------
__global__ void fc_kernel(const float* __restrict__ yfinal,
                          const float* __restrict__ fc_w,
                          const float* __restrict__ fc_b,
                          float* __restrict__ out)
{
    const int b = blockIdx.x;
    const int o = threadIdx.x;   // 0..95
    const float* h = yfinal + ((size_t)b * SEQ + (SEQ - 1)) * HIDDEN;
    const float* w = fc_w + (size_t)o * HIDDEN;
    float acc = fc_b[o];
#pragma unroll 16
    for (int k = 0; k < HIDDEN; k++) acc = fmaf(h[k], w[k], acc);
    out[b * OUTPUT_DIM + o] = acc;
}

// ---------------- host launch ----------------
extern "C" void kernel_launch(void* const* d_in, const int* in_sizes, int n_in,
                              void* d_out, int out_size)
{
    const float* x        = (const float*)d_in[0];  // [64,512,512]
    const float* w_ih0    = (const float*)d_in[1];  // [384,512]
    const float* w_ihrest = (const float*)d_in[2];  // [4,384,128]
    const float* w_hh     = (const float*)d_in[3];  // [5,384,128]
    const float* b_ih     = (const float*)d_in[4];  // [5,384]
    const float* b_hh     = (const float*)d_in[5];  // [5,384]
    const float* fc_w     = (const float*)d_in[6];  // [96,128]
    const float* fc_b     = (const float*)d_in[7];  // [96]
    float* out = (float*)d_out;

    float *gx, *ya, *yb;
    cudaGetSymbolAddress((void**)&gx, g_gx);
    cudaGetSymbolAddress((void**)&ya, g_ya);
    cudaGetSymbolAddress((void**)&yb, g_yb);

    const int M = BATCH * SEQ;                 // 32768
    dim3 ggrid(G3 / 64, M / 64);               // (6, 512)

    // layer 0
    gemm_nt_kernel<<<ggrid, 256>>>(x, w_ih0, b_ih, gx, M, INPUT_DIM);
    gru_rec_kernel<<<BATCH, 384>>>(w_hh, b_hh, ya);

    // layers 1..4 (ping-pong ya/yb)
    float* bufs[2] = { ya, yb };
    for (int l = 1; l < NUM_LAYERS; l++) {
        const float* src = bufs[(l - 1) & 1];
        float* dst = bufs[l & 1];
        gemm_nt_kernel<<<ggrid, 256>>>(src,
                                       w_ihrest + (size_t)(l - 1) * G3 * HIDDEN,
                                       b_ih + (size_t)l * G3, gx, M, HIDDEN);
        gru_rec_kernel<<<BATCH, 384>>>(w_hh + (size_t)l * G3 * HIDDEN,
                                       b_hh + (size_t)l * G3, dst);
    }

    // last layer output lives in bufs[(NUM_LAYERS-1)&1] == ya (l=4 even)
    fc_kernel<<<BATCH, OUTPUT_DIM>>>(bufs[(NUM_LAYERS - 1) & 1], fc_w, fc_b, out);
}

// round 2
// speedup vs baseline: 1.8589x; 1.8589x over previous
#include <cuda_runtime.h>
#include <math.h>

#define BATCH 64
#define SEQ 512
#define INPUT_DIM 512
#define HIDDEN 128
#define G3 384            // 3*HIDDEN
#define NUM_LAYERS 5
#define OUTPUT_DIM 96

typedef unsigned long long ull;

// ---------------- scratch (no allocs allowed) ----------------
__device__ float g_gx[BATCH * SEQ * G3];        // per-layer input gates
__device__ float g_ya[BATCH * SEQ * HIDDEN];    // ping
__device__ float g_yb[BATCH * SEQ * HIDDEN];    // pong

// ---------------- packed f32x2 helpers ----------------
__device__ __forceinline__ ull pk2(float a, float b) {
    ull r; asm("mov.b64 %0, {%1, %2};" : "=l"(r) : "f"(a), "f"(b)); return r;
}
__device__ __forceinline__ void upk2(ull v, float& a, float& b) {
    asm("mov.b64 {%0, %1}, %2;" : "=f"(a), "=f"(b) : "l"(v));
}
__device__ __forceinline__ ull ffma2(ull a, ull b, ull c) {
    ull d; asm("fma.rn.f32x2 %0, %1, %2, %3;" : "=l"(d) : "l"(a), "l"(b), "l"(c)); return d;
}

__device__ __forceinline__ float sigm_fast(float x) {
    // 1/(1+e^-x): MUFU.EX2-based exp + fast reciprocal
    float e = __expf(-x);
    return __fdividef(1.0f, 1.0f + e);
}
__device__ __forceinline__ float tanh_fast(float x) {
    // tanh(x) = 1 - 2e^{-2x}/(1+e^{-2x})
    float e = __expf(-2.0f * x);
    return 1.0f - __fdividef(2.0f * e, 1.0f + e);
}

// ---------------- GEMM: C[M x 384] = A[M x K] * W[384 x K]^T + bias ----------------
// BM=64, BN=64, BK=16, 256 threads, thread tile 4x4, packed f32x2 FMAs.
__global__ __launch_bounds__(256) void gemm_nt_kernel(
    const float* __restrict__ A, const float* __restrict__ W,
    const float* __restrict__ bias, float* __restrict__ C,
    int M, int K)
{
    __shared__ __align__(16) float Ast[16][64];
    __shared__ __align__(16) float Bst[16][64];

    const int tid = threadIdx.x;
    const int m0 = blockIdx.y * 64;
    const int n0 = blockIdx.x * 64;

    const int lrow = tid >> 2;          // 0..63
    const int lkc  = (tid & 3) << 2;    // 0,4,8,12

    const float* Ap = A + (size_t)(m0 + lrow) * K + lkc;
    const float* Wp = W + (size_t)(n0 + lrow) * K + lkc;

    const int tx = tid & 15;            // 0..15 (cols)
    const int ty = tid >> 4;            // 0..15 (rows)

    ull acc[4][2];
#pragma unroll
    for (int i = 0; i < 4; i++) { acc[i][0] = pk2(0.f, 0.f); acc[i][1] = pk2(0.f, 0.f); }

    float4 av = *(const float4*)(Ap);
    float4 bv = *(const float4*)(Wp);

    for (int kt = 0; kt < K; kt += 16) {
        __syncthreads();
        Ast[lkc + 0][lrow] = av.x; Ast[lkc + 1][lrow] = av.y;
        Ast[lkc + 2][lrow] = av.z; Ast[lkc + 3][lrow] = av.w;
        Bst[lkc + 0][lrow] = bv.x; Bst[lkc + 1][lrow] = bv.y;
        Bst[lkc + 2][lrow] = bv.z; Bst[lkc + 3][lrow] = bv.w;
        __syncthreads();

        if (kt + 16 < K) {
            av = *(const float4*)(Ap + kt + 16);
            bv = *(const float4*)(Wp + kt + 16);
        }

#pragma unroll
        for (int k = 0; k < 16; k++) {
            float4 a4 = *(const float4*)&Ast[k][ty << 2];
            ulonglong2 b2 = *(const ulonglong2*)&Bst[k][tx << 2];
            ull pa;
            pa = pk2(a4.x, a4.x);
            acc[0][0] = ffma2(pa, b2.x, acc[0][0]); acc[0][1] = ffma2(pa, b2.y, acc[0][1]);
            pa = pk2(a4.y, a4.y);
            acc[1][0] = ffma2(pa, b2.x, acc[1][0]); acc[1][1] = ffma2(pa, b2.y, acc[1][1]);
            pa = pk2(a4.z, a4.z);
            acc[2][0] = ffma2(pa, b2.x, acc[2][0]); acc[2][1] = ffma2(pa, b2.y, acc[2][1]);
            pa = pk2(a4.w, a4.w);
            acc[3][0] = ffma2(pa, b2.x, acc[3][0]); acc[3][1] = ffma2(pa, b2.y, acc[3][1]);
        }
    }

    // epilogue: add bias, store
#pragma unroll
    for (int i = 0; i < 4; i++) {
        int m = m0 + (ty << 2) + i;
        float c0, c1, c2, c3;
        upk2(acc[i][0], c0, c1);
        upk2(acc[i][1], c2, c3);
        int n = n0 + (tx << 2);
        float* Cp = C + (size_t)m * G3 + n;
        Cp[0] = c0 + bias[n + 0];
        Cp[1] = c1 + bias[n + 1];
        Cp[2] = c2 + bias[n + 2];
        Cp[3] = c3 + bias[n + 3];
    }
}

// ---------------- GRU recurrence: one CTA per batch element ----------------
// 384 threads; thread j owns gate-row j of w_hh (128 weights in registers,
// packed as 64 f32x2). Per step: gh[j] = b_hh[j] + w_hh[j,:]·h, barrier,
// 128 threads combine gates + write h, barrier.
// Optimizations vs R1: gx software-pipelined 1 step ahead (hides DRAM lat),
// 4 FFMA2 accumulator chains, single h buffer, h[j] register-resident for
// gate threads, MUFU-based fast sigmoid/tanh.
__global__ __launch_bounds__(384, 1) void gru_rec_kernel(
    const float* __restrict__ w_hh,   // [384][128] for this layer
    const float* __restrict__ b_hh,   // [384]
    float* __restrict__ y)            // [BATCH][SEQ][HIDDEN]
{
    __shared__ __align__(16) float h_s[HIDDEN];
    __shared__ float gh_s[G3];

    const int b = blockIdx.x;
    const int j = threadIdx.x;
    const bool gate_thr = (j < HIDDEN);

    // load this thread's weight row into registers (packed pairs)
    ull w2[64];
    {
        const float4* wr = (const float4*)(w_hh + (size_t)j * HIDDEN);
#pragma unroll
        for (int k4 = 0; k4 < 32; k4++) {
            float4 v = wr[k4];
            w2[2 * k4 + 0] = pk2(v.x, v.y);
            w2[2 * k4 + 1] = pk2(v.z, v.w);
        }
    }
    const float bh = b_hh[j];

    if (gate_thr) h_s[j] = 0.0f;

    const float* gxb = g_gx + (size_t)b * SEQ * G3;
    float* yb = y + (size_t)b * SEQ * HIDDEN;

    // prefetch t=0 gx
    float xr = 0.f, xz = 0.f, xn = 0.f;
    if (gate_thr) {
        xr = gxb[j];
        xz = gxb[j + HIDDEN];
        xn = gxb[j + 2 * HIDDEN];
    }
    float hreg = 0.0f;   // h[j] for gate threads (register-resident)
    __syncthreads();

    for (int t = 0; t < SEQ; t++) {
        // issue next step's gx loads immediately (full step to cover DRAM lat)
        float nxr = 0.f, nxz = 0.f, nxn = 0.f;
        if (gate_thr && t + 1 < SEQ) {
            const float* gxt1 = gxb + (t + 1) * G3;
            nxr = __ldg(gxt1 + j);
            nxz = __ldg(gxt1 + j + HIDDEN);
            nxn = __ldg(gxt1 + j + 2 * HIDDEN);
        }

        // gh[j] = bh + w_row_j · h   (4 independent FFMA2 chains)
        ull a0 = pk2(0.f, 0.f), a1 = pk2(0.f, 0.f);
        ull a2 = pk2(0.f, 0.f), a3 = pk2(0.f, 0.f);
        const ulonglong2* h2 = (const ulonglong2*)h_s;
#pragma unroll
        for (int k8 = 0; k8 < 16; k8++) {
            ulonglong2 hv0 = h2[2 * k8 + 0];
            ulonglong2 hv1 = h2[2 * k8 + 1];
            a0 = ffma2(w2[4 * k8 + 0], hv0.x, a0);
            a1 = ffma2(w2[4 * k8 + 1], hv0.y, a1);
            a2 = ffma2(w2[4 * k8 + 2], hv1.x, a2);
            a3 = ffma2(w2[4 * k8 + 3], hv1.y, a3);
        }
        a0 = ffma2(pk2(1.f, 1.f), a2, a0);   // a0 += a2 (packed add via fma)
        a1 = ffma2(pk2(1.f, 1.f), a3, a1);
        float l0, u0, l1, u1;
        upk2(a0, l0, u0);
        upk2(a1, l1, u1);
        gh_s[j] = bh + ((l0 + u0) + (l1 + u1));
        __syncthreads();

        if (gate_thr) {
            float r = sigm_fast(xr + gh_s[j]);
            float z = sigm_fast(xz + gh_s[j + HIDDEN]);
            float n = tanh_fast(xn + r * gh_s[j + 2 * HIDDEN]);
            float hn = (1.0f - z) * n + z * hreg;
            hreg = hn;
            h_s[j] = hn;          // safe: all matvec reads of h_s happened pre-barrier
            yb[t * HIDDEN + j] = hn;
        }
        __syncthreads();

        xr = nxr; xz = nxz; xn = nxn;
    }
}

// ---------------- final FC on last timestep ----------------
__global__ void fc_kernel(const float* __restrict__ yfinal,
                          const float* __restrict__ fc_w,
                          const float* __restrict__ fc_b,
                          float* __restrict__ out)
{
    const int b = blockIdx.x;
    const int o = threadIdx.x;   // 0..95
    const float* h = yfinal + ((size_t)b * SEQ + (SEQ - 1)) * HIDDEN;
    const float* w = fc_w + (size_t)o * HIDDEN;
    float acc = fc_b[o];
#pragma unroll 16
    for (int k = 0; k < HIDDEN; k++) acc = fmaf(h[k], w[k], acc);
    out[b * OUTPUT_DIM + o] = acc;
}

// ---------------- host launch ----------------
extern "C" void kernel_launch(void* const* d_in, const int* in_sizes, int n_in,
                              void* d_out, int out_size)
{
    const float* x        = (const float*)d_in[0];  // [64,512,512]
    const float* w_ih0    = (const float*)d_in[1];  // [384,512]
    const float* w_ihrest = (const float*)d_in[2];  // [4,384,128]
    const float* w_hh     = (const float*)d_in[3];  // [5,384,128]
    const float* b_ih     = (const float*)d_in[4];  // [5,384]
    const float* b_hh     = (const float*)d_in[5];  // [5,384]
    const float* fc_w     = (const float*)d_in[6];  // [96,128]
    const float* fc_b     = (const float*)d_in[7];  // [96]
    float* out = (float*)d_out;

    float *gx, *ya, *yb;
    cudaGetSymbolAddress((void**)&gx, g_gx);
    cudaGetSymbolAddress((void**)&ya, g_ya);
    cudaGetSymbolAddress((void**)&yb, g_yb);

    const int M = BATCH * SEQ;                 // 32768
    dim3 ggrid(G3 / 64, M / 64);               // (6, 512)

    // layer 0
    gemm_nt_kernel<<<ggrid, 256>>>(x, w_ih0, b_ih, gx, M, INPUT_DIM);
    gru_rec_kernel<<<BATCH, 384>>>(w_hh, b_hh, ya);

    // layers 1..4 (ping-pong ya/yb)
    float* bufs[2] = { ya, yb };
    for (int l = 1; l < NUM_LAYERS; l++) {
        const float* src = bufs[(l - 1) & 1];
        float* dst = bufs[l & 1];
        gemm_nt_kernel<<<ggrid, 256>>>(src,
                                       w_ihrest + (size_t)(l - 1) * G3 * HIDDEN,
                                       b_ih + (size_t)l * G3, gx, M, HIDDEN);
        gru_rec_kernel<<<BATCH, 384>>>(w_hh + (size_t)l * G3 * HIDDEN,
                                       b_hh + (size_t)l * G3, dst);
    }

    // last layer output lives in bufs[(NUM_LAYERS-1)&1] == ya (l=4 even)
    fc_kernel<<<BATCH, OUTPUT_DIM>>>(bufs[(NUM_LAYERS - 1) & 1], fc_w, fc_b, out);
}